// round 5
// baseline (speedup 1.0000x reference)
#include <cuda_runtime.h>
#include <math.h>

using u64 = unsigned long long;

// ---------------------------------------------------------------------------
// Packed fp32x2 helpers (sm_103a FFMA2 — only reachable via PTX).
// ---------------------------------------------------------------------------
__device__ __forceinline__ u64 pack_dup(float v) {
    u64 r; asm("mov.b64 %0, {%1, %1};" : "=l"(r) : "f"(v)); return r;
}
__device__ __forceinline__ void unpack2(u64 p, float& lo, float& hi) {
    asm("mov.b64 {%0, %1}, %2;" : "=f"(lo), "=f"(hi) : "l"(p));
}
__device__ __forceinline__ u64 ffma2(u64 a, u64 b, u64 c) {
    u64 d; asm("fma.rn.f32x2 %0, %1, %2, %3;" : "=l"(d) : "l"(a), "l"(b), "l"(c));
    return d;
}

// ---------------------------------------------------------------------------
// Scratch (no allocation allowed): masked weights.
// ---------------------------------------------------------------------------
__device__ float g_Wc[1024 * 1024];   // kernel * u_current            [D, U]
__device__ float g_Wp[1024 * 1024];   // recurrent_kernel * u_previous [U, U]

// ---------------------------------------------------------------------------
// Build masked weights. One block per unit (column u).
// ---------------------------------------------------------------------------
__global__ void build_mask_kernel(const float* __restrict__ W,
                                  const float* __restrict__ mu,
                                  const float* __restrict__ sigma,
                                  float* __restrict__ Wm,
                                  int n_in, int units, float scale) {
    int u = blockIdx.x;
    float m = mu[u];
    float s = sigma[u];
    s = fminf(fmaxf(s, 0.01f), 1.0f);
    float inv2s2 = 1.0f / (2.0f * s * s);
    float inv_nm1 = 1.0f / (float)(n_in - 1);

    float ss = 0.0f;
    for (int d = threadIdx.x; d < n_in; d += blockDim.x) {
        float diff = (float)d * inv_nm1 - m;
        float e = expf(-diff * diff * inv2s2);
        ss += e * e;
    }
    __shared__ float red[32];
    #pragma unroll
    for (int o = 16; o > 0; o >>= 1) ss += __shfl_down_sync(0xffffffffu, ss, o);
    if ((threadIdx.x & 31) == 0) red[threadIdx.x >> 5] = ss;
    __syncthreads();
    if (threadIdx.x < 32) {
        int nwarp = (blockDim.x + 31) >> 5;
        float v = (threadIdx.x < nwarp) ? red[threadIdx.x] : 0.0f;
        #pragma unroll
        for (int o = 16; o > 0; o >>= 1) v += __shfl_down_sync(0xffffffffu, v, o);
        if (threadIdx.x == 0) red[0] = v;
    }
    __syncthreads();
    float factor = scale * rsqrtf(red[0]);

    for (int d = threadIdx.x; d < n_in; d += blockDim.x) {
        float diff = (float)d * inv_nm1 - m;
        float e = expf(-diff * diff * inv2s2);
        Wm[(size_t)d * units + u] = W[(size_t)d * units + u] * (e * factor);
    }
}

// ---------------------------------------------------------------------------
// Big GEMM: C = A @ B + bias.  128x128x16 tiles, 256 threads, 8x8 micro-tile
// via FFMA2 (M-pairs).  (Unchanged from R2 — working, near its rt=3 ceiling.)
// ---------------------------------------------------------------------------
__global__ void __launch_bounds__(256) gemm_big_kernel(
    const float* __restrict__ A, int lda,
    const float* __restrict__ Bm,
    const float* __restrict__ bias,
    float* __restrict__ C, int ldc,
    int N, int K)
{
    __shared__ __align__(16) float As[16][128];   // transposed A tile [k][m]
    __shared__ __align__(16) float Bs[16][128];   // B tile [k][n]

    const int tid = threadIdx.x;
    const int tx = tid & 15;
    const int ty = tid >> 4;
    const int m0 = blockIdx.y * 128;
    const int n0 = blockIdx.x * 128;
    const int mt = ty * 8;
    const int nt = tx * 8;

    const int aRow = tid >> 2;
    const int aCol = (tid & 3) * 4;
    const int bRow = tid >> 5;
    const int bCol = (tid & 31) * 4;

    u64 acc[4][8];
    #pragma unroll
    for (int i = 0; i < 4; i++)
        #pragma unroll
        for (int j = 0; j < 8; j++) acc[i][j] = 0ull;

    for (int k0 = 0; k0 < K; k0 += 16) {
        #pragma unroll
        for (int r = 0; r < 2; r++) {
            int mr = aRow + r * 64;
            float4 v = *(const float4*)&A[(size_t)(m0 + mr) * lda + k0 + aCol];
            As[aCol + 0][mr] = v.x;
            As[aCol + 1][mr] = v.y;
            As[aCol + 2][mr] = v.z;
            As[aCol + 3][mr] = v.w;
        }
        #pragma unroll
        for (int r = 0; r < 2; r++) {
            int kr = bRow + r * 8;
            *(float4*)&Bs[kr][bCol] =
                *(const float4*)&Bm[(size_t)(k0 + kr) * N + n0 + bCol];
        }
        __syncthreads();

        #pragma unroll
        for (int kk = 0; kk < 16; kk++) {
            ulonglong2 a01 = *(const ulonglong2*)&As[kk][mt];
            ulonglong2 a23 = *(const ulonglong2*)&As[kk][mt + 4];
            float4 b0 = *(const float4*)&Bs[kk][nt];
            float4 b1 = *(const float4*)&Bs[kk][nt + 4];
            u64 ap[4] = {a01.x, a01.y, a23.x, a23.y};
            u64 bd[8] = {pack_dup(b0.x), pack_dup(b0.y), pack_dup(b0.z), pack_dup(b0.w),
                         pack_dup(b1.x), pack_dup(b1.y), pack_dup(b1.z), pack_dup(b1.w)};
            #pragma unroll
            for (int i = 0; i < 4; i++)
                #pragma unroll
                for (int j = 0; j < 8; j++)
                    acc[i][j] = ffma2(ap[i], bd[j], acc[i][j]);
        }
        __syncthreads();
    }

    float bv[8];
    {
        float4 b0 = *(const float4*)&bias[n0 + nt];
        float4 b1 = *(const float4*)&bias[n0 + nt + 4];
        bv[0] = b0.x; bv[1] = b0.y; bv[2] = b0.z; bv[3] = b0.w;
        bv[4] = b1.x; bv[5] = b1.y; bv[6] = b1.z; bv[7] = b1.w;
    }
    #pragma unroll
    for (int i = 0; i < 4; i++) {
        float lo[8], hi[8];
        #pragma unroll
        for (int j = 0; j < 8; j++) unpack2(acc[i][j], lo[j], hi[j]);
        const int mr = m0 + mt + 2 * i;
        float* c0 = &C[(size_t)mr * ldc + n0 + nt];
        float* c1 = &C[(size_t)(mr + 1) * ldc + n0 + nt];
        *(float4*)&c0[0] = make_float4(lo[0] + bv[0], lo[1] + bv[1], lo[2] + bv[2], lo[3] + bv[3]);
        *(float4*)&c0[4] = make_float4(lo[4] + bv[4], lo[5] + bv[5], lo[6] + bv[6], lo[7] + bv[7]);
        *(float4*)&c1[0] = make_float4(hi[0] + bv[0], hi[1] + bv[1], hi[2] + bv[2], hi[3] + bv[3]);
        *(float4*)&c1[4] = make_float4(hi[4] + bv[4], hi[5] + bv[5], hi[6] + bv[6], hi[7] + bv[7]);
    }
}

// ---------------------------------------------------------------------------
// Recurrent step GEMM v2: C[m,n] = tanh( C[m,n] + A[m,:] . B[:,n] ), in-place.
// BM=32, BN=64, BK=64, 256 threads, grid (N/64, B/32) = 128 CTAs (one wave).
// B tile stored DUPLICATED ((v,v) pairs) so the inner loop has no movs:
//   per kk per thread: 1 broadcast LDS.64 (A pair) + 2 LDS.128 (4 dup'd B)
//   + 4 FFMA2.  Double-buffered SMEM, one __syncthreads per 64-k tile.
// ---------------------------------------------------------------------------
#define STEP_SMEM_BYTES ((2 * 64 * 128 + 2 * 64 * 34) * 4)

__global__ void __launch_bounds__(256) gemm_step_kernel(
    const float* __restrict__ A, size_t lda,
    const float* __restrict__ Bm,
    float* __restrict__ C, size_t ldc,
    int N, int K)
{
    extern __shared__ float sm[];
    float* Bd[2] = { sm, sm + 64 * 128 };                       // [k][128] dup
    float* As[2] = { sm + 2 * 64 * 128, sm + 2 * 64 * 128 + 64 * 34 }; // [k][34]

    const int tid = threadIdx.x;
    const int tx = tid & 15;          // n-group: cols n0 + 4*tx .. +3
    const int ty = tid >> 4;          // m-pair:  rows m0 + 2*ty, +1   (0..15)
    const int m0 = blockIdx.y * 32;
    const int n0 = blockIdx.x * 64;

    // Loader mapping
    const int a_row = tid & 31;            // A: one row per lane (conflict-free STS)
    const int a_c4  = (tid >> 5) * 4;      // k-offset; second slot at +32
    const int b_k   = tid >> 4;            // B: k rows b_k + 16*i, i<4
    const int b_c4  = (tid & 15) * 4;      // 4 source cols

    float4 ra[2], rb[4];

    // --- prologue: tile 0 ---
    #pragma unroll
    for (int i = 0; i < 2; i++)
        ra[i] = *(const float4*)&A[(size_t)(m0 + a_row) * lda + a_c4 + 32 * i];
    #pragma unroll
    for (int i = 0; i < 4; i++)
        rb[i] = *(const float4*)&Bm[(size_t)(b_k + 16 * i) * N + n0 + b_c4];
    #pragma unroll
    for (int i = 0; i < 2; i++) {
        const int c = a_c4 + 32 * i;
        As[0][(c + 0) * 34 + a_row] = ra[i].x;
        As[0][(c + 1) * 34 + a_row] = ra[i].y;
        As[0][(c + 2) * 34 + a_row] = ra[i].z;
        As[0][(c + 3) * 34 + a_row] = ra[i].w;
    }
    #pragma unroll
    for (int i = 0; i < 4; i++) {
        float* p = &Bd[0][(b_k + 16 * i) * 128 + 2 * b_c4];
        *(float4*)&p[0] = make_float4(rb[i].x, rb[i].x, rb[i].y, rb[i].y);
        *(float4*)&p[4] = make_float4(rb[i].z, rb[i].z, rb[i].w, rb[i].w);
    }
    __syncthreads();

    u64 acc0 = 0ull, acc1 = 0ull, acc2 = 0ull, acc3 = 0ull;
    int s = 0;

    for (int tile = 0; tile < 16; tile++) {
        if (tile < 15) {
            const int k0 = (tile + 1) * 64;
            #pragma unroll
            for (int i = 0; i < 2; i++)
                ra[i] = *(const float4*)&A[(size_t)(m0 + a_row) * lda + k0 + a_c4 + 32 * i];
            #pragma unroll
            for (int i = 0; i < 4; i++)
                rb[i] = *(const float4*)&Bm[(size_t)(k0 + b_k + 16 * i) * N + n0 + b_c4];
        }

        const float* Ac = As[s];
        const float* Bc = Bd[s];
        #pragma unroll 4
        for (int kk = 0; kk < 64; kk++) {
            u64 a = *(const u64*)&Ac[kk * 34 + 2 * ty];
            ulonglong2 b0 = *(const ulonglong2*)&Bc[kk * 128 + 8 * tx];
            ulonglong2 b1 = *(const ulonglong2*)&Bc[kk * 128 + 8 * tx + 4];
            acc0 = ffma2(a, b0.x, acc0);
            acc1 = ffma2(a, b0.y, acc1);
            acc2 = ffma2(a, b1.x, acc2);
            acc3 = ffma2(a, b1.y, acc3);
        }

        if (tile < 15) {
            const int d = s ^ 1;
            #pragma unroll
            for (int i = 0; i < 2; i++) {
                const int c = a_c4 + 32 * i;
                As[d][(c + 0) * 34 + a_row] = ra[i].x;
                As[d][(c + 1) * 34 + a_row] = ra[i].y;
                As[d][(c + 2) * 34 + a_row] = ra[i].z;
                As[d][(c + 3) * 34 + a_row] = ra[i].w;
            }
            #pragma unroll
            for (int i = 0; i < 4; i++) {
                float* p = &Bd[d][(b_k + 16 * i) * 128 + 2 * b_c4];
                *(float4*)&p[0] = make_float4(rb[i].x, rb[i].x, rb[i].y, rb[i].y);
                *(float4*)&p[4] = make_float4(rb[i].z, rb[i].z, rb[i].w, rb[i].w);
            }
            __syncthreads();
            s = d;
        }
    }

    // Epilogue: += Z (already in C), tanh, store in place.
    const size_t mr = (size_t)(m0 + 2 * ty);
    float* p0 = C + mr * ldc + n0 + 4 * tx;
    float* p1 = p0 + ldc;
    float4 z0 = *(const float4*)p0;
    float4 z1 = *(const float4*)p1;
    float lo, hi;
    float4 o0, o1;
    unpack2(acc0, lo, hi); o0.x = tanhf(z0.x + lo); o1.x = tanhf(z1.x + hi);
    unpack2(acc1, lo, hi); o0.y = tanhf(z0.y + lo); o1.y = tanhf(z1.y + hi);
    unpack2(acc2, lo, hi); o0.z = tanhf(z0.z + lo); o1.z = tanhf(z1.z + hi);
    unpack2(acc3, lo, hi); o0.w = tanhf(z0.w + lo); o1.w = tanhf(z1.w + hi);
    *(float4*)p0 = o0;
    *(float4*)p1 = o1;
}

// ---------------------------------------------------------------------------
// Launch.
// Inputs: 0 inputs [B,T,D]  1 h0 [B,U]  2 kernel [D,U]  3 rec_kernel [U,U]
//         4 bias [U]  5 mu_c [U]  6 sigma_c [U]  7 mu_p [U]  8 sigma_p [U]
// Output: [B,T,U] float32.
// ---------------------------------------------------------------------------
extern "C" void kernel_launch(void* const* d_in, const int* in_sizes, int n_in,
                              void* d_out, int out_size) {
    const float* X    = (const float*)d_in[0];
    const float* h0   = (const float*)d_in[1];
    const float* Wk   = (const float*)d_in[2];
    const float* Wr   = (const float*)d_in[3];
    const float* bias = (const float*)d_in[4];
    const float* muc  = (const float*)d_in[5];
    const float* sic  = (const float*)d_in[6];
    const float* mup  = (const float*)d_in[7];
    const float* sip  = (const float*)d_in[8];
    float* out = (float*)d_out;

    const int U = in_sizes[4];
    const int D = in_sizes[2] / U;
    const int B = in_sizes[1] / U;
    const int T = in_sizes[0] / (B * D);

    float* Wc;
    float* Wp;
    cudaGetSymbolAddress((void**)&Wc, g_Wc);
    cudaGetSymbolAddress((void**)&Wp, g_Wp);

    static int s_attr_done = 0;
    if (!s_attr_done) {
        cudaFuncSetAttribute(gemm_step_kernel,
                             cudaFuncAttributeMaxDynamicSharedMemorySize,
                             STEP_SMEM_BYTES);
        s_attr_done = 1;
    }

    const float scale = sqrtf((float)D);  // reference uses sqrt(D) for BOTH masks

    // 1) Masked weights.
    build_mask_kernel<<<U, 256>>>(Wk, muc, sic, Wc, D, U, scale);
    build_mask_kernel<<<U, 256>>>(Wr, mup, sip, Wp, U, U, scale);

    // 2) Z = X @ Wc + bias -> straight into d_out.
    {
        dim3 grid(U / 128, (B * T) / 128);
        gemm_big_kernel<<<grid, 256>>>(X, D, Wc, bias, out, U, U, D);
    }

    // 3) Recurrent scan: out[:,t,:] = tanh(Z_t + h_{t-1} @ Wp), one launch/step.
    {
        dim3 grid(U / 64, B / 32);   // 16 x 8 = 128 CTAs (one full wave)
        const size_t ldo = (size_t)T * U;
        for (int t = 0; t < T; t++) {
            const float*  A   = (t == 0) ? h0 : (out + (size_t)(t - 1) * U);
            const size_t  lda = (t == 0) ? (size_t)U : ldo;
            float* Ct = out + (size_t)t * U;   // Z term (in place)
            gemm_step_kernel<<<grid, 256, STEP_SMEM_BYTES>>>(
                A, lda, Wp, Ct, ldo, U, U);
        }
    }
}

// round 6
// speedup vs baseline: 1.4724x; 1.4724x over previous
#include <cuda_runtime.h>
#include <math.h>

using u64 = unsigned long long;

// ---------------------------------------------------------------------------
// Packed fp32x2 helpers (sm_103a FFMA2 — only reachable via PTX).
// ---------------------------------------------------------------------------
__device__ __forceinline__ u64 pack_dup(float v) {
    u64 r; asm("mov.b64 %0, {%1, %1};" : "=l"(r) : "f"(v)); return r;
}
__device__ __forceinline__ void unpack2(u64 p, float& lo, float& hi) {
    asm("mov.b64 {%0, %1}, %2;" : "=f"(lo), "=f"(hi) : "l"(p));
}
__device__ __forceinline__ u64 ffma2(u64 a, u64 b, u64 c) {
    u64 d; asm("fma.rn.f32x2 %0, %1, %2, %3;" : "=l"(d) : "l"(a), "l"(b), "l"(c));
    return d;
}

// ---------------------------------------------------------------------------
// Scratch (no allocation allowed): masked weights.
// ---------------------------------------------------------------------------
__device__ float g_Wc[1024 * 1024];   // kernel * u_current            [D, U]
__device__ float g_Wp[1024 * 1024];   // recurrent_kernel * u_previous [U, U]

// ---------------------------------------------------------------------------
// Build masked weights. One block per unit (column u).
// ---------------------------------------------------------------------------
__global__ void build_mask_kernel(const float* __restrict__ W,
                                  const float* __restrict__ mu,
                                  const float* __restrict__ sigma,
                                  float* __restrict__ Wm,
                                  int n_in, int units, float scale) {
    int u = blockIdx.x;
    float m = mu[u];
    float s = sigma[u];
    s = fminf(fmaxf(s, 0.01f), 1.0f);
    float inv2s2 = 1.0f / (2.0f * s * s);
    float inv_nm1 = 1.0f / (float)(n_in - 1);

    float ss = 0.0f;
    for (int d = threadIdx.x; d < n_in; d += blockDim.x) {
        float diff = (float)d * inv_nm1 - m;
        float e = expf(-diff * diff * inv2s2);
        ss += e * e;
    }
    __shared__ float red[32];
    #pragma unroll
    for (int o = 16; o > 0; o >>= 1) ss += __shfl_down_sync(0xffffffffu, ss, o);
    if ((threadIdx.x & 31) == 0) red[threadIdx.x >> 5] = ss;
    __syncthreads();
    if (threadIdx.x < 32) {
        int nwarp = (blockDim.x + 31) >> 5;
        float v = (threadIdx.x < nwarp) ? red[threadIdx.x] : 0.0f;
        #pragma unroll
        for (int o = 16; o > 0; o >>= 1) v += __shfl_down_sync(0xffffffffu, v, o);
        if (threadIdx.x == 0) red[0] = v;
    }
    __syncthreads();
    float factor = scale * rsqrtf(red[0]);

    for (int d = threadIdx.x; d < n_in; d += blockDim.x) {
        float diff = (float)d * inv_nm1 - m;
        float e = expf(-diff * diff * inv2s2);
        Wm[(size_t)d * units + u] = W[(size_t)d * units + u] * (e * factor);
    }
}

// ---------------------------------------------------------------------------
// Big GEMM: C = A @ B + bias.  128x128x16 tiles, 256 threads, 8x8 micro-tile
// via FFMA2 (M-pairs).  (Known-good from R2 — near its rt=3 ceiling.)
// ---------------------------------------------------------------------------
__global__ void __launch_bounds__(256) gemm_big_kernel(
    const float* __restrict__ A, int lda,
    const float* __restrict__ Bm,
    const float* __restrict__ bias,
    float* __restrict__ C, int ldc,
    int N, int K)
{
    __shared__ __align__(16) float As[16][128];   // transposed A tile [k][m]
    __shared__ __align__(16) float Bs[16][128];   // B tile [k][n]

    const int tid = threadIdx.x;
    const int tx = tid & 15;
    const int ty = tid >> 4;
    const int m0 = blockIdx.y * 128;
    const int n0 = blockIdx.x * 128;
    const int mt = ty * 8;
    const int nt = tx * 8;

    const int aRow = tid >> 2;
    const int aCol = (tid & 3) * 4;
    const int bRow = tid >> 5;
    const int bCol = (tid & 31) * 4;

    u64 acc[4][8];
    #pragma unroll
    for (int i = 0; i < 4; i++)
        #pragma unroll
        for (int j = 0; j < 8; j++) acc[i][j] = 0ull;

    for (int k0 = 0; k0 < K; k0 += 16) {
        #pragma unroll
        for (int r = 0; r < 2; r++) {
            int mr = aRow + r * 64;
            float4 v = *(const float4*)&A[(size_t)(m0 + mr) * lda + k0 + aCol];
            As[aCol + 0][mr] = v.x;
            As[aCol + 1][mr] = v.y;
            As[aCol + 2][mr] = v.z;
            As[aCol + 3][mr] = v.w;
        }
        #pragma unroll
        for (int r = 0; r < 2; r++) {
            int kr = bRow + r * 8;
            *(float4*)&Bs[kr][bCol] =
                *(const float4*)&Bm[(size_t)(k0 + kr) * N + n0 + bCol];
        }
        __syncthreads();

        #pragma unroll
        for (int kk = 0; kk < 16; kk++) {
            ulonglong2 a01 = *(const ulonglong2*)&As[kk][mt];
            ulonglong2 a23 = *(const ulonglong2*)&As[kk][mt + 4];
            float4 b0 = *(const float4*)&Bs[kk][nt];
            float4 b1 = *(const float4*)&Bs[kk][nt + 4];
            u64 ap[4] = {a01.x, a01.y, a23.x, a23.y};
            u64 bd[8] = {pack_dup(b0.x), pack_dup(b0.y), pack_dup(b0.z), pack_dup(b0.w),
                         pack_dup(b1.x), pack_dup(b1.y), pack_dup(b1.z), pack_dup(b1.w)};
            #pragma unroll
            for (int i = 0; i < 4; i++)
                #pragma unroll
                for (int j = 0; j < 8; j++)
                    acc[i][j] = ffma2(ap[i], bd[j], acc[i][j]);
        }
        __syncthreads();
    }

    float bv[8];
    {
        float4 b0 = *(const float4*)&bias[n0 + nt];
        float4 b1 = *(const float4*)&bias[n0 + nt + 4];
        bv[0] = b0.x; bv[1] = b0.y; bv[2] = b0.z; bv[3] = b0.w;
        bv[4] = b1.x; bv[5] = b1.y; bv[6] = b1.z; bv[7] = b1.w;
    }
    #pragma unroll
    for (int i = 0; i < 4; i++) {
        float lo[8], hi[8];
        #pragma unroll
        for (int j = 0; j < 8; j++) unpack2(acc[i][j], lo[j], hi[j]);
        const int mr = m0 + mt + 2 * i;
        float* c0 = &C[(size_t)mr * ldc + n0 + nt];
        float* c1 = &C[(size_t)(mr + 1) * ldc + n0 + nt];
        *(float4*)&c0[0] = make_float4(lo[0] + bv[0], lo[1] + bv[1], lo[2] + bv[2], lo[3] + bv[3]);
        *(float4*)&c0[4] = make_float4(lo[4] + bv[4], lo[5] + bv[5], lo[6] + bv[6], lo[7] + bv[7]);
        *(float4*)&c1[0] = make_float4(hi[0] + bv[0], hi[1] + bv[1], hi[2] + bv[2], hi[3] + bv[3]);
        *(float4*)&c1[4] = make_float4(hi[4] + bv[4], hi[5] + bv[5], hi[6] + bv[6], hi[7] + bv[7]);
    }
}

// ---------------------------------------------------------------------------
// Recurrent step GEMM v3 (N-paired FFMA2): C = tanh(C + A @ B), in-place.
// BM=32, BN=64, BK=64, 256 threads, grid (N/64, B/32) = 128 CTAs (one wave).
// Accumulator pairs are (n, n+1): B read directly as contiguous u64 pairs
// from a NORMAL tile (no duplication, no movs); A stored pre-duplicated
// ((a,a) per m) — it is the broadcast operand so crossbar cost dedups.
// Inner loop per thread per kk: 2x LDS.128 + 4x FFMA2.
// Bs rows padded to 68 floats to kill store-phase bank conflicts.
// ---------------------------------------------------------------------------
#define STEP_SMEM_BYTES ((2 * 64 * 64 + 2 * 64 * 68) * 4)   /* 66 KB */

__global__ void __launch_bounds__(256) gemm_step_kernel(
    const float* __restrict__ A, size_t lda,
    const float* __restrict__ Bm,
    float* __restrict__ C, size_t ldc,
    int N, int K)
{
    extern __shared__ float sm[];
    float* Ad[2] = { sm, sm + 64 * 64 };                         // [k][64] dup'd
    float* Bs[2] = { sm + 2 * 64 * 64, sm + 2 * 64 * 64 + 64 * 68 }; // [k][68]

    const int tid = threadIdx.x;
    const int tx = tid & 15;          // n-group: cols n0 + 4*tx .. +3 (2 pairs)
    const int ty = tid >> 4;          // m-pair:  rows m0 + 2*ty, +1   (0..15)
    const int m0 = blockIdx.y * 32;
    const int n0 = blockIdx.x * 64;

    // Loader mapping
    const int a_row = tid & 31;            // A row within tile
    const int a_c8  = (tid >> 5) * 8;      // 8 consecutive k per thread
    const int b_row = tid >> 2;            // B k-row (0..63)
    const int b_c   = (tid & 3) * 16;      // 16 consecutive n per thread

    float4 ra[2], rb[4];

    // --- prologue: tile 0 ---
    #pragma unroll
    for (int i = 0; i < 2; i++)
        ra[i] = *(const float4*)&A[(size_t)(m0 + a_row) * lda + a_c8 + 4 * i];
    #pragma unroll
    for (int i = 0; i < 4; i++)
        rb[i] = *(const float4*)&Bm[(size_t)b_row * N + n0 + b_c + 4 * i];
    {
        const float av[8] = {ra[0].x, ra[0].y, ra[0].z, ra[0].w,
                             ra[1].x, ra[1].y, ra[1].z, ra[1].w};
        #pragma unroll
        for (int j = 0; j < 8; j++)
            *(u64*)&Ad[0][(a_c8 + j) * 64 + 2 * a_row] = pack_dup(av[j]);
        #pragma unroll
        for (int i = 0; i < 4; i++)
            *(float4*)&Bs[0][b_row * 68 + b_c + 4 * i] = rb[i];
    }
    __syncthreads();

    u64 acc00 = 0ull, acc01 = 0ull, acc10 = 0ull, acc11 = 0ull;
    int s = 0;

    for (int tile = 0; tile < 16; tile++) {
        if (tile < 15) {
            const int k0 = (tile + 1) * 64;
            #pragma unroll
            for (int i = 0; i < 2; i++)
                ra[i] = *(const float4*)&A[(size_t)(m0 + a_row) * lda + k0 + a_c8 + 4 * i];
            #pragma unroll
            for (int i = 0; i < 4; i++)
                rb[i] = *(const float4*)&Bm[(size_t)(k0 + b_row) * N + n0 + b_c + 4 * i];
        }

        const float* Ac = Ad[s];
        const float* Bc = Bs[s];
        #pragma unroll 8
        for (int kk = 0; kk < 64; kk++) {
            ulonglong2 av = *(const ulonglong2*)&Ac[kk * 64 + 4 * ty]; // (a0,a0),(a1,a1)
            ulonglong2 bv = *(const ulonglong2*)&Bc[kk * 68 + 4 * tx]; // (b0,b1),(b2,b3)
            acc00 = ffma2(av.x, bv.x, acc00);
            acc01 = ffma2(av.x, bv.y, acc01);
            acc10 = ffma2(av.y, bv.x, acc10);
            acc11 = ffma2(av.y, bv.y, acc11);
        }

        if (tile < 15) {
            const int d = s ^ 1;
            const float av[8] = {ra[0].x, ra[0].y, ra[0].z, ra[0].w,
                                 ra[1].x, ra[1].y, ra[1].z, ra[1].w};
            #pragma unroll
            for (int j = 0; j < 8; j++)
                *(u64*)&Ad[d][(a_c8 + j) * 64 + 2 * a_row] = pack_dup(av[j]);
            #pragma unroll
            for (int i = 0; i < 4; i++)
                *(float4*)&Bs[d][b_row * 68 + b_c + 4 * i] = rb[i];
            __syncthreads();
            s = d;
        }
    }

    // Epilogue: += Z (already in C), tanh, store in place.
    // acc00/acc01 hold (n,n+1)/(n+2,n+3) of row m0+2ty; acc10/acc11 of +1.
    const size_t mr = (size_t)(m0 + 2 * ty);
    float* p0 = C + mr * ldc + n0 + 4 * tx;
    float* p1 = p0 + ldc;
    float4 z0 = *(const float4*)p0;
    float4 z1 = *(const float4*)p1;
    float a, b;
    float4 o0, o1;
    unpack2(acc00, a, b); o0.x = tanhf(z0.x + a); o0.y = tanhf(z0.y + b);
    unpack2(acc01, a, b); o0.z = tanhf(z0.z + a); o0.w = tanhf(z0.w + b);
    unpack2(acc10, a, b); o1.x = tanhf(z1.x + a); o1.y = tanhf(z1.y + b);
    unpack2(acc11, a, b); o1.z = tanhf(z1.z + a); o1.w = tanhf(z1.w + b);
    *(float4*)p0 = o0;
    *(float4*)p1 = o1;
}

// ---------------------------------------------------------------------------
// Launch.
// Inputs: 0 inputs [B,T,D]  1 h0 [B,U]  2 kernel [D,U]  3 rec_kernel [U,U]
//         4 bias [U]  5 mu_c [U]  6 sigma_c [U]  7 mu_p [U]  8 sigma_p [U]
// Output: [B,T,U] float32.
// ---------------------------------------------------------------------------
extern "C" void kernel_launch(void* const* d_in, const int* in_sizes, int n_in,
                              void* d_out, int out_size) {
    const float* X    = (const float*)d_in[0];
    const float* h0   = (const float*)d_in[1];
    const float* Wk   = (const float*)d_in[2];
    const float* Wr   = (const float*)d_in[3];
    const float* bias = (const float*)d_in[4];
    const float* muc  = (const float*)d_in[5];
    const float* sic  = (const float*)d_in[6];
    const float* mup  = (const float*)d_in[7];
    const float* sip  = (const float*)d_in[8];
    float* out = (float*)d_out;

    const int U = in_sizes[4];
    const int D = in_sizes[2] / U;
    const int B = in_sizes[1] / U;
    const int T = in_sizes[0] / (B * D);

    float* Wc;
    float* Wp;
    cudaGetSymbolAddress((void**)&Wc, g_Wc);
    cudaGetSymbolAddress((void**)&Wp, g_Wp);

    static int s_attr_done = 0;
    if (!s_attr_done) {
        cudaFuncSetAttribute(gemm_step_kernel,
                             cudaFuncAttributeMaxDynamicSharedMemorySize,
                             STEP_SMEM_BYTES);
        s_attr_done = 1;
    }

    const float scale = sqrtf((float)D);  // reference uses sqrt(D) for BOTH masks

    // 1) Masked weights.
    build_mask_kernel<<<U, 256>>>(Wk, muc, sic, Wc, D, U, scale);
    build_mask_kernel<<<U, 256>>>(Wr, mup, sip, Wp, U, U, scale);

    // 2) Z = X @ Wc + bias -> straight into d_out.
    {
        dim3 grid(U / 128, (B * T) / 128);
        gemm_big_kernel<<<grid, 256>>>(X, D, Wc, bias, out, U, U, D);
    }

    // 3) Recurrent scan: out[:,t,:] = tanh(Z_t + h_{t-1} @ Wp), one launch/step.
    {
        dim3 grid(U / 64, B / 32);   // 16 x 8 = 128 CTAs (one full wave)
        const size_t ldo = (size_t)T * U;
        for (int t = 0; t < T; t++) {
            const float*  A   = (t == 0) ? h0 : (out + (size_t)(t - 1) * U);
            const size_t  lda = (t == 0) ? (size_t)U : ldo;
            float* Ct = out + (size_t)t * U;   // Z term (in place)
            gemm_step_kernel<<<grid, 256, STEP_SMEM_BYTES>>>(
                A, lda, Wp, Ct, ldo, U, U);
        }
    }
}

// round 7
// speedup vs baseline: 4.6849x; 3.1818x over previous
#include <cuda_runtime.h>
#include <cuda_bf16.h>
#include <math.h>

// ---------------------------------------------------------------------------
// Static scratch (no allocation allowed): bf16 hi/lo split masked weights.
// Layout [K][N] row-major (same as source fp32 weights).
// ---------------------------------------------------------------------------
__device__ __nv_bfloat16 g_Wc_hi[1024 * 1024];
__device__ __nv_bfloat16 g_Wc_lo[1024 * 1024];
__device__ __nv_bfloat16 g_Wp_hi[1024 * 1024];
__device__ __nv_bfloat16 g_Wp_lo[1024 * 1024];

// ---------------------------------------------------------------------------
// MMA / ldmatrix primitives (sm_80+ semantics, runs as HMMA on sm_103a).
// ---------------------------------------------------------------------------
__device__ __forceinline__ void ldsm4(unsigned r[4], unsigned addr) {
    asm volatile("ldmatrix.sync.aligned.m8n8.x4.shared.b16 {%0,%1,%2,%3}, [%4];"
                 : "=r"(r[0]), "=r"(r[1]), "=r"(r[2]), "=r"(r[3]) : "r"(addr));
}
__device__ __forceinline__ void ldsm4t(unsigned r[4], unsigned addr) {
    asm volatile("ldmatrix.sync.aligned.m8n8.x4.trans.shared.b16 {%0,%1,%2,%3}, [%4];"
                 : "=r"(r[0]), "=r"(r[1]), "=r"(r[2]), "=r"(r[3]) : "r"(addr));
}
__device__ __forceinline__ void mma16816(float d[4], const unsigned a[4],
                                         const unsigned b[2]) {
    asm volatile(
        "mma.sync.aligned.m16n8k16.row.col.f32.bf16.bf16.f32 "
        "{%0,%1,%2,%3}, {%4,%5,%6,%7}, {%8,%9}, {%0,%1,%2,%3};"
        : "+f"(d[0]), "+f"(d[1]), "+f"(d[2]), "+f"(d[3])
        : "r"(a[0]), "r"(a[1]), "r"(a[2]), "r"(a[3]), "r"(b[0]), "r"(b[1]));
}
__device__ __forceinline__ unsigned pack_bf(__nv_bfloat16 a, __nv_bfloat16 b) {
    unsigned short ua = *(unsigned short*)&a;
    unsigned short ub = *(unsigned short*)&b;
    return (unsigned)ua | ((unsigned)ub << 16);
}
// Split v into bf16 hi + lo; returns packed pair for two consecutive values.
__device__ __forceinline__ void split2(float v0, float v1,
                                       unsigned& hi, unsigned& lo) {
    __nv_bfloat16 h0 = __float2bfloat16_rn(v0);
    __nv_bfloat16 h1 = __float2bfloat16_rn(v1);
    __nv_bfloat16 l0 = __float2bfloat16_rn(v0 - __bfloat162float(h0));
    __nv_bfloat16 l1 = __float2bfloat16_rn(v1 - __bfloat162float(h1));
    hi = pack_bf(h0, h1);
    lo = pack_bf(l0, l1);
}

// ---------------------------------------------------------------------------
// Build masked weights, split into bf16 hi/lo. One block per unit (column u).
// ---------------------------------------------------------------------------
__global__ void build_mask_kernel(const float* __restrict__ W,
                                  const float* __restrict__ mu,
                                  const float* __restrict__ sigma,
                                  __nv_bfloat16* __restrict__ Whi,
                                  __nv_bfloat16* __restrict__ Wlo,
                                  int n_in, int units, float scale) {
    int u = blockIdx.x;
    float m = mu[u];
    float s = sigma[u];
    s = fminf(fmaxf(s, 0.01f), 1.0f);
    float inv2s2 = 1.0f / (2.0f * s * s);
    float inv_nm1 = 1.0f / (float)(n_in - 1);

    float ss = 0.0f;
    for (int d = threadIdx.x; d < n_in; d += blockDim.x) {
        float diff = (float)d * inv_nm1 - m;
        float e = expf(-diff * diff * inv2s2);
        ss += e * e;
    }
    __shared__ float red[32];
    #pragma unroll
    for (int o = 16; o > 0; o >>= 1) ss += __shfl_down_sync(0xffffffffu, ss, o);
    if ((threadIdx.x & 31) == 0) red[threadIdx.x >> 5] = ss;
    __syncthreads();
    if (threadIdx.x < 32) {
        int nwarp = (blockDim.x + 31) >> 5;
        float v = (threadIdx.x < nwarp) ? red[threadIdx.x] : 0.0f;
        #pragma unroll
        for (int o = 16; o > 0; o >>= 1) v += __shfl_down_sync(0xffffffffu, v, o);
        if (threadIdx.x == 0) red[0] = v;
    }
    __syncthreads();
    float factor = scale * rsqrtf(red[0]);

    for (int d = threadIdx.x; d < n_in; d += blockDim.x) {
        float diff = (float)d * inv_nm1 - m;
        float e = expf(-diff * diff * inv2s2);
        float w = W[(size_t)d * units + u] * (e * factor);
        __nv_bfloat16 h = __float2bfloat16_rn(w);
        __nv_bfloat16 l = __float2bfloat16_rn(w - __bfloat162float(h));
        Whi[(size_t)d * units + u] = h;
        Wlo[(size_t)d * units + u] = l;
    }
}

// ---------------------------------------------------------------------------
// bf16-split MMA GEMM.
//   C[m,n] = epi( sum_k A[m,k]*B[k,n] )
//   A fp32 (split to hi/lo bf16 in-kernel); B pre-split bf16 planes [K][N].
//   STEP=false: epi = +bias[n]            (big GEMM, writes C)
//   STEP=true : epi = tanhf(C[m,n] + acc) (in-place recurrent step)
// Tiles: BM = 32*M16 (64 or 32), BN=64, BK=32.  256 threads, 8 warps (2m x 4n),
// warp tile = (16*M16) x 16.  Double-buffered SMEM, one syncthreads/iter.
// SMEM pitches: A 112B/row (16B-aligned, ldmatrix conflict-free),
//               B 144B/row (idem).
// ---------------------------------------------------------------------------
template <int M16, bool STEP>
__global__ void __launch_bounds__(256) mma_gemm(
    const float* A, size_t lda,
    const __nv_bfloat16* __restrict__ Bhi_g,
    const __nv_bfloat16* __restrict__ Blo_g,
    const float* __restrict__ bias,
    float* C, size_t ldc, int N, int K)
{
    constexpr int BM = 32 * M16;
    constexpr int APITCH = 112;               // bytes per A smem row (56 bf16)
    constexpr int BPITCH = 144;               // bytes per B smem row (72 bf16)
    constexpr int A_PL = BM * APITCH;         // one A plane
    constexpr int B_PL = 32 * BPITCH;         // one B plane
    constexpr int STAGE = 2 * A_PL + 2 * B_PL;

    extern __shared__ char smem[];
    const unsigned sbase = (unsigned)__cvta_generic_to_shared(smem);

    const int tid  = threadIdx.x;
    const int lane = tid & 31;
    const int wid  = tid >> 5;
    const int wm   = wid & 1;                 // warp m index (0..1)
    const int wn   = wid >> 1;                // warp n index (0..3)
    const int m0   = blockIdx.y * BM;
    const int n0   = blockIdx.x * 64;

    // ---- global prefetch registers ----
    float4 ra0, ra1;
    uint4  rbh, rbl;

    // ---- per-warp ldmatrix base addresses (bytes, within stage 0) ----
    const unsigned aBase = sbase + (unsigned)((wm * 16 * M16 + (lane & 15)) * APITCH
                                              + (lane >> 4) * 16);
    const unsigned bBase = sbase + (unsigned)(2 * A_PL + (lane & 15) * BPITCH
                                              + (lane >> 4) * 16 + wn * 32);

    float accH[M16][2][4];
    float accX[M16][2][4];
    #pragma unroll
    for (int i = 0; i < M16; i++)
        #pragma unroll
        for (int j = 0; j < 2; j++)
            #pragma unroll
            for (int q = 0; q < 4; q++) { accH[i][j][q] = 0.f; accX[i][j][q] = 0.f; }

    // ---------------- loaders ----------------
    auto ldgA = [&](int k0) {
        if constexpr (M16 == 2) {
            const float* p = A + (size_t)(m0 + (tid >> 2)) * lda + k0 + (tid & 3) * 8;
            ra0 = *(const float4*)p;
            ra1 = *(const float4*)(p + 4);
        } else {
            const float* p = A + (size_t)(m0 + (tid >> 3)) * lda + k0 + (tid & 7) * 4;
            ra0 = *(const float4*)p;
        }
    };
    auto ldgB = [&](int k0) {
        size_t off = (size_t)(k0 + (tid >> 3)) * N + n0 + (tid & 7) * 8;
        rbh = *(const uint4*)(Bhi_g + off);
        rbl = *(const uint4*)(Blo_g + off);
    };
    auto stsAB = [&](int st) {
        char* base = smem + st * STAGE;
        if constexpr (M16 == 2) {
            const int row = tid >> 2, kc = (tid & 3) * 8;
            unsigned h0, l0, h1, l1, h2, l2, h3, l3;
            split2(ra0.x, ra0.y, h0, l0);
            split2(ra0.z, ra0.w, h1, l1);
            split2(ra1.x, ra1.y, h2, l2);
            split2(ra1.z, ra1.w, h3, l3);
            *(uint2*)(base + row * APITCH + kc * 2)            = make_uint2(h0, h1);
            *(uint2*)(base + row * APITCH + kc * 2 + 8)        = make_uint2(h2, h3);
            *(uint2*)(base + A_PL + row * APITCH + kc * 2)     = make_uint2(l0, l1);
            *(uint2*)(base + A_PL + row * APITCH + kc * 2 + 8) = make_uint2(l2, l3);
        } else {
            const int row = tid >> 3, kc = (tid & 7) * 4;
            unsigned h0, l0, h1, l1;
            split2(ra0.x, ra0.y, h0, l0);
            split2(ra0.z, ra0.w, h1, l1);
            *(uint2*)(base + row * APITCH + kc * 2)        = make_uint2(h0, h1);
            *(uint2*)(base + A_PL + row * APITCH + kc * 2) = make_uint2(l0, l1);
        }
        const int krow = tid >> 3, nc = (tid & 7) * 8;
        *(uint4*)(base + 2 * A_PL + krow * BPITCH + nc * 2)        = rbh;
        *(uint4*)(base + 2 * A_PL + B_PL + krow * BPITCH + nc * 2) = rbl;
    };

    // ---------------- compute on one stage ----------------
    auto compute = [&](int st) {
        const unsigned sOff = (unsigned)(st * STAGE);
        #pragma unroll
        for (int c = 0; c < 2; c++) {                 // two k16 chunks
            unsigned ah[M16][4], al[M16][4], bh[4], bl[4];
            #pragma unroll
            for (int i = 0; i < M16; i++) {
                ldsm4(ah[i], aBase + sOff + i * (16 * APITCH) + c * 32);
                ldsm4(al[i], aBase + sOff + A_PL + i * (16 * APITCH) + c * 32);
            }
            ldsm4t(bh, bBase + sOff + c * (16 * BPITCH));
            ldsm4t(bl, bBase + sOff + B_PL + c * (16 * BPITCH));
            #pragma unroll
            for (int i = 0; i < M16; i++)
                #pragma unroll
                for (int j = 0; j < 2; j++) {
                    mma16816(accH[i][j], ah[i], bh + 2 * j);
                    mma16816(accX[i][j], ah[i], bl + 2 * j);
                    mma16816(accX[i][j], al[i], bh + 2 * j);
                }
        }
    };

    // ---------------- mainloop ----------------
    const int NIT = K / 32;
    ldgA(0); ldgB(0);
    stsAB(0);
    __syncthreads();
    int s = 0;
    for (int it = 0; it < NIT; it++) {
        if (it + 1 < NIT) { ldgA((it + 1) * 32); ldgB((it + 1) * 32); }
        compute(s);
        if (it + 1 < NIT) {
            stsAB(s ^ 1);
            __syncthreads();
            s ^= 1;
        }
    }

    // ---------------- epilogue ----------------
    #pragma unroll
    for (int i = 0; i < M16; i++) {
        const int mBase = m0 + wm * 16 * M16 + i * 16 + (lane >> 2);
        #pragma unroll
        for (int j = 0; j < 2; j++) {
            const int nBase = n0 + wn * 16 + j * 8 + 2 * (lane & 3);
            #pragma unroll
            for (int h = 0; h < 2; h++) {          // row halves +0 / +8
                const int m = mBase + h * 8;
                float d0 = accH[i][j][2 * h + 0] + accX[i][j][2 * h + 0];
                float d1 = accH[i][j][2 * h + 1] + accX[i][j][2 * h + 1];
                float* p = C + (size_t)m * ldc + nBase;
                if constexpr (STEP) {
                    float2 z = *(float2*)p;
                    float2 o;
                    o.x = tanhf(z.x + d0);
                    o.y = tanhf(z.y + d1);
                    *(float2*)p = o;
                } else {
                    float2 o;
                    o.x = d0 + bias[nBase];
                    o.y = d1 + bias[nBase + 1];
                    *(float2*)p = o;
                }
            }
        }
    }
}

// ---------------------------------------------------------------------------
// Launch.
// Inputs: 0 inputs [B,T,D]  1 h0 [B,U]  2 kernel [D,U]  3 rec_kernel [U,U]
//         4 bias [U]  5 mu_c [U]  6 sigma_c [U]  7 mu_p [U]  8 sigma_p [U]
// Output: [B,T,U] float32.
// ---------------------------------------------------------------------------
extern "C" void kernel_launch(void* const* d_in, const int* in_sizes, int n_in,
                              void* d_out, int out_size) {
    const float* X    = (const float*)d_in[0];
    const float* h0   = (const float*)d_in[1];
    const float* Wk   = (const float*)d_in[2];
    const float* Wr   = (const float*)d_in[3];
    const float* bias = (const float*)d_in[4];
    const float* muc  = (const float*)d_in[5];
    const float* sic  = (const float*)d_in[6];
    const float* mup  = (const float*)d_in[7];
    const float* sip  = (const float*)d_in[8];
    float* out = (float*)d_out;

    const int U = in_sizes[4];
    const int D = in_sizes[2] / U;
    const int B = in_sizes[1] / U;
    const int T = in_sizes[0] / (B * D);

    __nv_bfloat16 *Wc_hi, *Wc_lo, *Wp_hi, *Wp_lo;
    cudaGetSymbolAddress((void**)&Wc_hi, g_Wc_hi);
    cudaGetSymbolAddress((void**)&Wc_lo, g_Wc_lo);
    cudaGetSymbolAddress((void**)&Wp_hi, g_Wp_hi);
    cudaGetSymbolAddress((void**)&Wp_lo, g_Wp_lo);

    // SMEM sizes: big (M16=2): 2*(64*112) + 2*(32*144) = 23552/stage -> 47104
    //             step (M16=1): 2*(32*112) + 2*(32*144) = 16384/stage -> 32768
    const int SMEM_BIG  = 2 * (2 * 64 * 112 + 2 * 32 * 144);
    const int SMEM_STEP = 2 * (2 * 32 * 112 + 2 * 32 * 144);
    static int s_attr_done = 0;
    if (!s_attr_done) {
        cudaFuncSetAttribute(mma_gemm<2, false>,
                             cudaFuncAttributeMaxDynamicSharedMemorySize, SMEM_BIG);
        cudaFuncSetAttribute(mma_gemm<1, true>,
                             cudaFuncAttributeMaxDynamicSharedMemorySize, SMEM_STEP);
        s_attr_done = 1;
    }

    const float scale = sqrtf((float)D);  // reference uses sqrt(D) for BOTH masks

    // 1) Masked weights, split to bf16 hi/lo.
    build_mask_kernel<<<U, 256>>>(Wk, muc, sic, Wc_hi, Wc_lo, D, U, scale);
    build_mask_kernel<<<U, 256>>>(Wr, mup, sip, Wp_hi, Wp_lo, U, U, scale);

    // 2) Z = X @ Wc + bias -> straight into d_out.
    {
        dim3 grid(U / 64, (B * T) / 64);     // 16 x 2048
        mma_gemm<2, false><<<grid, 256, SMEM_BIG>>>(
            X, (size_t)D, Wc_hi, Wc_lo, bias, out, (size_t)U, U, D);
    }

    // 3) Recurrent scan: out[:,t,:] = tanh(Z_t + h_{t-1} @ Wp), one launch/step.
    {
        dim3 grid(U / 64, B / 32);           // 16 x 8 = 128 CTAs (one wave)
        const size_t ldo = (size_t)T * U;
        for (int t = 0; t < T; t++) {
            const float* A   = (t == 0) ? h0 : (out + (size_t)(t - 1) * U);
            const size_t lda = (t == 0) ? (size_t)U : ldo;
            float* Ct = out + (size_t)t * U;   // Z term (in place)
            mma_gemm<1, true><<<grid, 256, SMEM_STEP>>>(
                A, lda, Wp_hi, Wp_lo, nullptr, Ct, ldo, U, U);
        }
    }
}